// round 4
// baseline (speedup 1.0000x reference)
#include <cuda_runtime.h>
#include <math.h>
#include <float.h>
#include <stdint.h>

// ---------------- problem constants ----------------
#define BB    2
#define TT    2048
#define CDIM  1024
#define NH    16
#define HD    64
#define MTOT  (BB*TT)          // 4096
#define N3C   (3*CDIM)         // 3072
#define RANK  16
#define LSCALE 2.0f            // alpha/rank = 32/16

typedef unsigned long long u64;

// ---------------- f32x2 helpers (sm_103a packed fp32) ----------------
__device__ __forceinline__ void ffma2(u64 &d, u64 a, u64 b) {
    asm("fma.rn.f32x2 %0, %1, %2, %0;" : "+l"(d) : "l"(a), "l"(b));
}
__device__ __forceinline__ u64 fmul2(u64 a, u64 b) {
    u64 d; asm("mul.rn.f32x2 %0, %1, %2;" : "=l"(d) : "l"(a), "l"(b)); return d;
}
__device__ __forceinline__ u64 dup2(float x) {
    u64 r; asm("mov.b64 %0, {%1, %1};" : "=l"(r) : "f"(x)); return r;
}
__device__ __forceinline__ float2 unpk(u64 v) {
    float lo, hi; asm("mov.b64 {%0, %1}, %2;" : "=f"(lo), "=f"(hi) : "l"(v));
    return make_float2(lo, hi);
}

// ---------------- scratch (device globals; no allocation allowed) ----------------
__device__ float g_qkv [MTOT * N3C];    // 48 MB: q | fq(k) | fq(v)
__device__ float g_attn[MTOT * CDIM];   // 16 MB
__device__ float g_mid [MTOT * RANK];
__device__ float g_mid2[MTOT * RANK];

// ---------------- rank-16 LoRA mid: out[m, r] = sum_k A[m,k]*la[k,r] ----------------
__global__ __launch_bounds__(256) void lora_mid_kernel(
    const float* __restrict__ A, const float* __restrict__ la,
    float* __restrict__ out, int K)
{
    int warp = blockIdx.x * (blockDim.x >> 5) + (threadIdx.x >> 5);
    int lane = threadIdx.x & 31;
    const float* a = A + (size_t)warp * K;
    float acc[RANK];
#pragma unroll
    for (int r = 0; r < RANK; r++) acc[r] = 0.0f;
    for (int k = lane; k < K; k += 32) {
        float av = a[k];
        const float* lp = la + (size_t)k * RANK;
#pragma unroll
        for (int r = 0; r < RANK; r++) acc[r] += av * lp[r];
    }
#pragma unroll
    for (int r = 0; r < RANK; r++) {
#pragma unroll
        for (int o = 16; o >= 1; o >>= 1)
            acc[r] += __shfl_xor_sync(0xffffffffu, acc[r], o);
    }
    if (lane < RANK) out[(size_t)warp * RANK + lane] = acc[lane];
}

// ---------------- fused GEMM: C = A@W + bias + 2*(mid@lb), optional fake-quant ----------------
// BM=128, BN=64, BK=16, 256 threads, 8x4 per thread via f32x2.
__global__ __launch_bounds__(256) void gemm_lora_kernel(
    const float* __restrict__ A, const float* __restrict__ W,
    const float* __restrict__ bias,
    const float* __restrict__ mid, const float* __restrict__ lb,
    float* __restrict__ C,
    int N, int K, int quant_start,
    const float* __restrict__ qsp, const float* __restrict__ qzp)
{
    const int BM = 128, BN = 64, BK = 16;
    __shared__ __align__(16) float As[BK][BM];        // 8 KB (A transposed)
    __shared__ __align__(16) float Bs[BK][BN * 2];    // 8 KB (W duplicated)
    __shared__ __align__(16) float mids[BM][RANK];    // 8 KB
    __shared__ __align__(16) float lbs[RANK][BN];     // 4 KB

    int tid = threadIdx.x;
    int tx = tid & 15, ty = tid >> 4;
    int m0 = blockIdx.y * BM, n0 = blockIdx.x * BN;

    u64 acc[4][4];
#pragma unroll
    for (int i = 0; i < 4; i++)
#pragma unroll
        for (int j = 0; j < 4; j++) acc[i][j] = 0ull;

    // loader assignments
    int lrow = tid >> 1;            // 0..127
    int lko  = (tid & 1) * 8;       // 0 or 8
    const float* ga = A + (size_t)(m0 + lrow) * K + lko;
    int bk = tid >> 4;              // 0..15
    int bn = (tid & 15) * 4;        // 0..60
    const float* gw = W + (size_t)bk * N + n0 + bn;

    for (int kt = 0; kt < K; kt += BK) {
        float4 a0 = *(const float4*)(ga + kt);
        float4 a1 = *(const float4*)(ga + kt + 4);
        As[lko + 0][lrow] = a0.x; As[lko + 1][lrow] = a0.y;
        As[lko + 2][lrow] = a0.z; As[lko + 3][lrow] = a0.w;
        As[lko + 4][lrow] = a1.x; As[lko + 5][lrow] = a1.y;
        As[lko + 6][lrow] = a1.z; As[lko + 7][lrow] = a1.w;
        float4 w4 = *(const float4*)(gw + (size_t)kt * N);
        *(float2*)&Bs[bk][2 * bn + 0] = make_float2(w4.x, w4.x);
        *(float2*)&Bs[bk][2 * bn + 2] = make_float2(w4.y, w4.y);
        *(float2*)&Bs[bk][2 * bn + 4] = make_float2(w4.z, w4.z);
        *(float2*)&Bs[bk][2 * bn + 6] = make_float2(w4.w, w4.w);
        __syncthreads();
#pragma unroll
        for (int kk = 0; kk < BK; kk++) {
            ulonglong2 aA = *(const ulonglong2*)&As[kk][ty * 8];
            ulonglong2 aB = *(const ulonglong2*)&As[kk][ty * 8 + 4];
            ulonglong2 b0 = *(const ulonglong2*)&Bs[kk][tx * 8];
            ulonglong2 b1 = *(const ulonglong2*)&Bs[kk][tx * 8 + 4];
            u64 aa[4] = { aA.x, aA.y, aB.x, aB.y };
            u64 bb[4] = { b0.x, b0.y, b1.x, b1.y };
#pragma unroll
            for (int rp = 0; rp < 4; rp++)
#pragma unroll
                for (int c = 0; c < 4; c++)
                    ffma2(acc[rp][c], aa[rp], bb[c]);
        }
        __syncthreads();
    }

    // ---- epilogue: LoRA + bias + optional fake-quant ----
    {
        int r2 = tid >> 1; int h8 = (tid & 1) * 8;
        const float* gm = mid + (size_t)(m0 + r2) * RANK + h8;
        *(float4*)&mids[r2][h8]     = *(const float4*)gm;
        *(float4*)&mids[r2][h8 + 4] = *(const float4*)(gm + 4);
        int lr = tid >> 4;
        const float* gl = lb + (size_t)lr * N + n0 + (tid & 15) * 4;
        *(float4*)&lbs[lr][(tid & 15) * 4] = *(const float4*)gl;
    }
    __syncthreads();

    float res[8][4];
#pragma unroll
    for (int rp = 0; rp < 4; rp++)
#pragma unroll
        for (int j = 0; j < 4; j++) {
            float2 v = unpk(acc[rp][j]);
            res[2 * rp][j] = v.x; res[2 * rp + 1][j] = v.y;
        }

    float qs = *qsp, qz = *qzp;
    float bv[4];
#pragma unroll
    for (int j = 0; j < 4; j++) bv[j] = bias[n0 + tx * 4 + j];

#pragma unroll
    for (int i = 0; i < 8; i++) {
        int row = m0 + ty * 8 + i;
#pragma unroll
        for (int j = 0; j < 4; j++) {
            int col = n0 + tx * 4 + j;
            float lv = 0.0f;
#pragma unroll
            for (int r = 0; r < RANK; r++)
                lv += mids[ty * 8 + i][r] * lbs[r][tx * 4 + j];
            float v = res[i][j] + bv[j] + LSCALE * lv;
            if (col >= quant_start) {
                float q = rintf(__fdiv_rn(v, qs) + qz);   // RNE == jnp.round
                q = fminf(fmaxf(q, 0.0f), 255.0f);
                v = (q - qz) * qs;
            }
            res[i][j] = v;
        }
        *(float4*)&C[(size_t)row * N + n0 + tx * 4] =
            make_float4(res[i][0], res[i][1], res[i][2], res[i][3]);
    }
}

// ---------------- flash attention, fp32 + f32x2 ----------------
// grid (B*H, T/64), 256 threads, 64x64 tiles, streaming softmax.
// smem: Qs[d][r] 64x68, Kd[d][2c] dup 64x136 (reused as Pd[r][2k] 64x132), Vs[c][d] 64x68.
#define QS 68
#define KS 136
#define PS 132
#define VS 68
#define ATTN_SMEM ((64 * (QS + KS + VS)) * 4)   // 69632 bytes

__global__ __launch_bounds__(256) void attn_kernel(
    const float* __restrict__ qkv, float* __restrict__ out)
{
    extern __shared__ __align__(16) float sm[];
    float* Qs = sm;
    float* Kd = sm + 64 * QS;
    float* Vs = Kd + 64 * KS;

    int tid = threadIdx.x;
    int tx = tid & 15, ty = tid >> 4;
    int bh = blockIdx.x;
    int b = bh >> 4, h = bh & 15;
    int qb = (int)gridDim.y - 1 - (int)blockIdx.y;   // big blocks first

    const float* qbase = qkv + (size_t)(b * TT) * N3C + h * HD;

    // load Q transposed: Qs[d][r]
    {
        int r  = tid >> 2;
        int d0 = (tid & 3) * 16;
        const float* gq = qbase + (size_t)(qb * 64 + r) * N3C + d0;
#pragma unroll
        for (int c4 = 0; c4 < 4; c4++) {
            float4 v = *(const float4*)(gq + c4 * 4);
            int d = d0 + c4 * 4;
            Qs[(d + 0) * QS + r] = v.x; Qs[(d + 1) * QS + r] = v.y;
            Qs[(d + 2) * QS + r] = v.z; Qs[(d + 3) * QS + r] = v.w;
        }
    }

    u64 accO[4][2];
    float mrow[4], lrow[4];
#pragma unroll
    for (int i = 0; i < 4; i++) {
        accO[i][0] = 0ull; accO[i][1] = 0ull;
        mrow[i] = -FLT_MAX; lrow[i] = 0.0f;
    }

    for (int j = 0; j <= qb; j++) {
        // load K (dup, transposed) and V (natural)
        {
            int c  = tid >> 2;
            int d0 = (tid & 3) * 16;
            const float* gk = qbase + CDIM     + (size_t)(j * 64 + c) * N3C + d0;
            const float* gv = qbase + 2 * CDIM + (size_t)(j * 64 + c) * N3C + d0;
#pragma unroll
            for (int q4 = 0; q4 < 4; q4++) {
                int d = d0 + q4 * 4;
                float4 kv = *(const float4*)(gk + q4 * 4);
                *(float2*)&Kd[(d + 0) * KS + 2 * c] = make_float2(kv.x, kv.x);
                *(float2*)&Kd[(d + 1) * KS + 2 * c] = make_float2(kv.y, kv.y);
                *(float2*)&Kd[(d + 2) * KS + 2 * c] = make_float2(kv.z, kv.z);
                *(float2*)&Kd[(d + 3) * KS + 2 * c] = make_float2(kv.w, kv.w);
                *(float4*)&Vs[c * VS + d] = *(const float4*)(gv + q4 * 4);
            }
        }
        __syncthreads();

        // S = Q K^T  (rows paired from Qs, cols dup'd from Kd)
        u64 accS[2][4];
#pragma unroll
        for (int rp = 0; rp < 2; rp++)
#pragma unroll
            for (int c = 0; c < 4; c++) accS[rp][c] = 0ull;
#pragma unroll 8
        for (int d = 0; d < 64; d++) {
            ulonglong2 qa  = *(const ulonglong2*)&Qs[d * QS + ty * 4];
            ulonglong2 kb0 = *(const ulonglong2*)&Kd[d * KS + tx * 8];
            ulonglong2 kb1 = *(const ulonglong2*)&Kd[d * KS + tx * 8 + 4];
            u64 bb[4] = { kb0.x, kb0.y, kb1.x, kb1.y };
#pragma unroll
            for (int c = 0; c < 4; c++) {
                ffma2(accS[0][c], qa.x, bb[c]);
                ffma2(accS[1][c], qa.y, bb[c]);
            }
        }

        float s[4][4];
#pragma unroll
        for (int rp = 0; rp < 2; rp++)
#pragma unroll
            for (int c = 0; c < 4; c++) {
                float2 v = unpk(accS[rp][c]);
                s[2 * rp][c]     = v.x * 0.125f;
                s[2 * rp + 1][c] = v.y * 0.125f;
            }
        if (j == qb) {   // causal mask on the diagonal tile
#pragma unroll
            for (int i = 0; i < 4; i++)
#pragma unroll
                for (int c = 0; c < 4; c++)
                    if (tx * 4 + c > ty * 4 + i) s[i][c] = -FLT_MAX;
        }

        __syncthreads();   // all Kd reads done before P overwrites it

        // streaming softmax (row stats replicated across the 16-lane tx group)
        float pr[4][4];
#pragma unroll
        for (int i = 0; i < 4; i++) {
            float mx = fmaxf(fmaxf(s[i][0], s[i][1]), fmaxf(s[i][2], s[i][3]));
#pragma unroll
            for (int o = 8; o >= 1; o >>= 1)
                mx = fmaxf(mx, __shfl_xor_sync(0xffffffffu, mx, o));
            float mnew  = fmaxf(mrow[i], mx);
            float alpha = __expf(mrow[i] - mnew);
            mrow[i] = mnew;
            float rs = 0.0f;
#pragma unroll
            for (int c = 0; c < 4; c++) {
                float p = __expf(s[i][c] - mnew);
                pr[i][c] = p; rs += p;
            }
#pragma unroll
            for (int o = 8; o >= 1; o >>= 1)
                rs += __shfl_xor_sync(0xffffffffu, rs, o);
            lrow[i] = lrow[i] * alpha + rs;
            u64 a2 = dup2(alpha);
            accO[i][0] = fmul2(accO[i][0], a2);
            accO[i][1] = fmul2(accO[i][1], a2);
        }

        // store P row-major, duplicated along k: Pd[r][2k]
#pragma unroll
        for (int i = 0; i < 4; i++)
#pragma unroll
            for (int c = 0; c < 4; c++)
                *(float2*)&Kd[(ty * 4 + i) * PS + (tx * 4 + c) * 2] =
                    make_float2(pr[i][c], pr[i][c]);
        __syncthreads();

        // O += P V
#pragma unroll 8
        for (int k = 0; k < 64; k++) {
            u64 pa[4];
#pragma unroll
            for (int i = 0; i < 4; i++)
                pa[i] = *(const u64*)&Kd[(ty * 4 + i) * PS + 2 * k];
            ulonglong2 vb = *(const ulonglong2*)&Vs[k * VS + tx * 4];
#pragma unroll
            for (int i = 0; i < 4; i++) {
                ffma2(accO[i][0], pa[i], vb.x);
                ffma2(accO[i][1], pa[i], vb.y);
            }
        }
        __syncthreads();   // before next tile overwrites Kd/Vs
    }

    // finalize: divide by l, write [B,T,C]
    float* ob = out + (size_t)(b * TT + qb * 64) * CDIM + h * HD;
#pragma unroll
    for (int i = 0; i < 4; i++) {
        float inv = __fdiv_rn(1.0f, lrow[i]);
        float2 o0 = unpk(accO[i][0]);
        float2 o1 = unpk(accO[i][1]);
        *(float4*)&ob[(size_t)(ty * 4 + i) * CDIM + tx * 4] =
            make_float4(o0.x * inv, o0.y * inv, o1.x * inv, o1.y * inv);
    }
}

// ---------------- launch ----------------
extern "C" void kernel_launch(void* const* d_in, const int* in_sizes, int n_in,
                              void* d_out, int out_size)
{
    const float* x       = (const float*)d_in[0];
    const float* w_attn  = (const float*)d_in[1];
    const float* b_attn  = (const float*)d_in[2];
    const float* la_attn = (const float*)d_in[3];
    const float* lb_attn = (const float*)d_in[4];
    const float* w_proj  = (const float*)d_in[5];
    const float* b_proj  = (const float*)d_in[6];
    const float* la_proj = (const float*)d_in[7];
    const float* lb_proj = (const float*)d_in[8];
    const float* ksc     = (const float*)d_in[9];
    const float* kzp     = (const float*)d_in[10];
    float* out = (float*)d_out;

    void *p_qkv, *p_attn, *p_mid, *p_mid2;
    cudaGetSymbolAddress(&p_qkv,  g_qkv);
    cudaGetSymbolAddress(&p_attn, g_attn);
    cudaGetSymbolAddress(&p_mid,  g_mid);
    cudaGetSymbolAddress(&p_mid2, g_mid2);
    float* qkv  = (float*)p_qkv;
    float* attn = (float*)p_attn;
    float* mid  = (float*)p_mid;
    float* mid2 = (float*)p_mid2;

    cudaFuncSetAttribute(attn_kernel,
                         cudaFuncAttributeMaxDynamicSharedMemorySize, ATTN_SMEM);

    // 1) LoRA mid for QKV
    lora_mid_kernel<<<MTOT / 8, 256>>>(x, la_attn, mid, CDIM);
    // 2) QKV GEMM + bias + LoRA + fake-quant on K,V columns (>= 1024)
    gemm_lora_kernel<<<dim3(N3C / 64, MTOT / 128), 256>>>(
        x, w_attn, b_attn, mid, lb_attn, qkv, N3C, CDIM, CDIM, ksc, kzp);
    // 3) causal attention
    attn_kernel<<<dim3(BB * NH, TT / 64), 256, ATTN_SMEM>>>(qkv, attn);
    // 4) LoRA mid for proj
    lora_mid_kernel<<<MTOT / 8, 256>>>(attn, la_proj, mid2, CDIM);
    // 5) output projection (no quant)
    gemm_lora_kernel<<<dim3(CDIM / 64, MTOT / 128), 256>>>(
        attn, w_proj, b_proj, mid2, lb_proj, out, CDIM, CDIM, 1 << 30, ksc, kzp);
}

// round 5
// speedup vs baseline: 1.6206x; 1.6206x over previous
#include <cuda_runtime.h>
#include <math.h>
#include <float.h>
#include <stdint.h>

// ---------------- problem constants ----------------
#define BB    2
#define TT    2048
#define CDIM  1024
#define NH    16
#define HD    64
#define MTOT  (BB*TT)          // 4096
#define N3C   (3*CDIM)         // 3072
#define RANK  16
#define LSCALE 2.0f            // alpha/rank = 32/16

typedef unsigned long long u64;

// ---------------- f32x2 helpers (sm_103a packed fp32) ----------------
__device__ __forceinline__ void ffma2(u64 &d, u64 a, u64 b) {
    asm("fma.rn.f32x2 %0, %1, %2, %0;" : "+l"(d) : "l"(a), "l"(b));
}
__device__ __forceinline__ u64 fmul2(u64 a, u64 b) {
    u64 d; asm("mul.rn.f32x2 %0, %1, %2;" : "=l"(d) : "l"(a), "l"(b)); return d;
}
__device__ __forceinline__ u64 dup2(float x) {
    u64 r; asm("mov.b64 %0, {%1, %1};" : "=l"(r) : "f"(x)); return r;
}
__device__ __forceinline__ float2 unpk(u64 v) {
    float lo, hi; asm("mov.b64 {%0, %1}, %2;" : "=f"(lo), "=f"(hi) : "l"(v));
    return make_float2(lo, hi);
}

// ---------------- scratch (device globals; no allocation allowed) ----------------
__device__ float g_qkv [MTOT * N3C];    // 48 MB: q | fq(k) | fq(v)
__device__ float g_attn[MTOT * CDIM];   // 16 MB
__device__ float g_mid [MTOT * RANK];
__device__ float g_mid2[MTOT * RANK];

// ---------------- rank-16 LoRA mid: out[m, r] = sum_k A[m,k]*la[k,r] ----------------
__global__ __launch_bounds__(256) void lora_mid_kernel(
    const float* __restrict__ A, const float* __restrict__ la,
    float* __restrict__ out, int K)
{
    int warp = blockIdx.x * (blockDim.x >> 5) + (threadIdx.x >> 5);
    int lane = threadIdx.x & 31;
    const float* a = A + (size_t)warp * K;
    float acc[RANK];
#pragma unroll
    for (int r = 0; r < RANK; r++) acc[r] = 0.0f;
    for (int k = lane; k < K; k += 32) {
        float av = a[k];
        const float* lp = la + (size_t)k * RANK;
#pragma unroll
        for (int r = 0; r < RANK; r++) acc[r] += av * lp[r];
    }
#pragma unroll
    for (int r = 0; r < RANK; r++) {
#pragma unroll
        for (int o = 16; o >= 1; o >>= 1)
            acc[r] += __shfl_xor_sync(0xffffffffu, acc[r], o);
    }
    if (lane < RANK) out[(size_t)warp * RANK + lane] = acc[lane];
}

// ---------------- fused GEMM: C = A@W + bias + 2*(mid@lb), optional fake-quant ----------------
// BM=128, BN=64, BK=16, 256 threads, 8x4 per thread via f32x2.
__global__ __launch_bounds__(256) void gemm_lora_kernel(
    const float* __restrict__ A, const float* __restrict__ W,
    const float* __restrict__ bias,
    const float* __restrict__ mid, const float* __restrict__ lb,
    float* __restrict__ C,
    int N, int K, int quant_start,
    const float* __restrict__ qsp, const float* __restrict__ qzp)
{
    const int BM = 128, BN = 64, BK = 16;
    __shared__ __align__(16) float As[BK][BM];        // 8 KB (A transposed)
    __shared__ __align__(16) float Bs[BK][BN * 2];    // 8 KB (W duplicated)
    __shared__ __align__(16) float mids[BM][RANK];    // 8 KB
    __shared__ __align__(16) float lbs[RANK][BN];     // 4 KB

    int tid = threadIdx.x;
    int tx = tid & 15, ty = tid >> 4;
    int m0 = blockIdx.y * BM, n0 = blockIdx.x * BN;

    u64 acc[4][4];
#pragma unroll
    for (int i = 0; i < 4; i++)
#pragma unroll
        for (int j = 0; j < 4; j++) acc[i][j] = 0ull;

    // loader assignments
    int lrow = tid >> 1;            // 0..127
    int lko  = (tid & 1) * 8;       // 0 or 8
    const float* ga = A + (size_t)(m0 + lrow) * K + lko;
    int bk = tid >> 4;              // 0..15
    int bn = (tid & 15) * 4;        // 0..60
    const float* gw = W + (size_t)bk * N + n0 + bn;

    for (int kt = 0; kt < K; kt += BK) {
        float4 a0 = *(const float4*)(ga + kt);
        float4 a1 = *(const float4*)(ga + kt + 4);
        As[lko + 0][lrow] = a0.x; As[lko + 1][lrow] = a0.y;
        As[lko + 2][lrow] = a0.z; As[lko + 3][lrow] = a0.w;
        As[lko + 4][lrow] = a1.x; As[lko + 5][lrow] = a1.y;
        As[lko + 6][lrow] = a1.z; As[lko + 7][lrow] = a1.w;
        float4 w4 = *(const float4*)(gw + (size_t)kt * N);
        *(float2*)&Bs[bk][2 * bn + 0] = make_float2(w4.x, w4.x);
        *(float2*)&Bs[bk][2 * bn + 2] = make_float2(w4.y, w4.y);
        *(float2*)&Bs[bk][2 * bn + 4] = make_float2(w4.z, w4.z);
        *(float2*)&Bs[bk][2 * bn + 6] = make_float2(w4.w, w4.w);
        __syncthreads();
#pragma unroll
        for (int kk = 0; kk < BK; kk++) {
            ulonglong2 aA = *(const ulonglong2*)&As[kk][ty * 8];
            ulonglong2 aB = *(const ulonglong2*)&As[kk][ty * 8 + 4];
            ulonglong2 b0 = *(const ulonglong2*)&Bs[kk][tx * 8];
            ulonglong2 b1 = *(const ulonglong2*)&Bs[kk][tx * 8 + 4];
            u64 aa[4] = { aA.x, aA.y, aB.x, aB.y };
            u64 bb[4] = { b0.x, b0.y, b1.x, b1.y };
#pragma unroll
            for (int rp = 0; rp < 4; rp++)
#pragma unroll
                for (int c = 0; c < 4; c++)
                    ffma2(acc[rp][c], aa[rp], bb[c]);
        }
        __syncthreads();
    }

    // ---- epilogue: LoRA + bias + optional fake-quant ----
    {
        int r2 = tid >> 1; int h8 = (tid & 1) * 8;
        const float* gm = mid + (size_t)(m0 + r2) * RANK + h8;
        *(float4*)&mids[r2][h8]     = *(const float4*)gm;
        *(float4*)&mids[r2][h8 + 4] = *(const float4*)(gm + 4);
        int lr = tid >> 4;
        const float* gl = lb + (size_t)lr * N + n0 + (tid & 15) * 4;
        *(float4*)&lbs[lr][(tid & 15) * 4] = *(const float4*)gl;
    }
    __syncthreads();

    float res[8][4];
#pragma unroll
    for (int rp = 0; rp < 4; rp++)
#pragma unroll
        for (int j = 0; j < 4; j++) {
            float2 v = unpk(acc[rp][j]);
            res[2 * rp][j] = v.x; res[2 * rp + 1][j] = v.y;
        }

    float qs = *qsp, qz = *qzp;
    float bv[4];
#pragma unroll
    for (int j = 0; j < 4; j++) bv[j] = bias[n0 + tx * 4 + j];

#pragma unroll
    for (int i = 0; i < 8; i++) {
        int row = m0 + ty * 8 + i;
#pragma unroll
        for (int j = 0; j < 4; j++) {
            int col = n0 + tx * 4 + j;
            float lv = 0.0f;
#pragma unroll
            for (int r = 0; r < RANK; r++)
                lv += mids[ty * 8 + i][r] * lbs[r][tx * 4 + j];
            float v = res[i][j] + bv[j] + LSCALE * lv;
            if (col >= quant_start) {
                float q = rintf(__fdiv_rn(v, qs) + qz);   // RNE == jnp.round
                q = fminf(fmaxf(q, 0.0f), 255.0f);
                v = (q - qz) * qs;
            }
            res[i][j] = v;
        }
        *(float4*)&C[(size_t)row * N + n0 + tx * 4] =
            make_float4(res[i][0], res[i][1], res[i][2], res[i][3]);
    }
}

// ---------------- flash attention, fp32 + f32x2 ----------------
// grid (B*H, T/64), 256 threads, 64x64 tiles, streaming softmax.
// smem: Qs[d][r] 64x68, Kd[d][2c] dup 64x136 (reused as Pd[r][2k] 64x132), Vs[c][d] 64x68.
#define QS 68
#define KS 136
#define PS 132
#define VS 68
#define ATTN_SMEM ((64 * (QS + KS + VS)) * 4)   // 69632 bytes

__global__ __launch_bounds__(256) void attn_kernel(
    const float* __restrict__ qkv, float* __restrict__ out)
{
    extern __shared__ __align__(16) float sm[];
    float* Qs = sm;
    float* Kd = sm + 64 * QS;
    float* Vs = Kd + 64 * KS;

    int tid = threadIdx.x;
    int tx = tid & 15, ty = tid >> 4;
    int bh = blockIdx.x;
    int b = bh >> 4, h = bh & 15;
    int qb = (int)gridDim.y - 1 - (int)blockIdx.y;   // big blocks first

    const float* qbase = qkv + (size_t)(b * TT) * N3C + h * HD;

    // load Q transposed: Qs[d][r]
    {
        int r  = tid >> 2;
        int d0 = (tid & 3) * 16;
        const float* gq = qbase + (size_t)(qb * 64 + r) * N3C + d0;
#pragma unroll
        for (int c4 = 0; c4 < 4; c4++) {
            float4 v = *(const float4*)(gq + c4 * 4);
            int d = d0 + c4 * 4;
            Qs[(d + 0) * QS + r] = v.x; Qs[(d + 1) * QS + r] = v.y;
            Qs[(d + 2) * QS + r] = v.z; Qs[(d + 3) * QS + r] = v.w;
        }
    }

    u64 accO[4][2];
    float mrow[4], lrow[4];
#pragma unroll
    for (int i = 0; i < 4; i++) {
        accO[i][0] = 0ull; accO[i][1] = 0ull;
        mrow[i] = -FLT_MAX; lrow[i] = 0.0f;
    }

    for (int j = 0; j <= qb; j++) {
        // load K (dup, transposed) and V (natural)
        {
            int c  = tid >> 2;
            int d0 = (tid & 3) * 16;
            const float* gk = qbase + CDIM     + (size_t)(j * 64 + c) * N3C + d0;
            const float* gv = qbase + 2 * CDIM + (size_t)(j * 64 + c) * N3C + d0;
#pragma unroll
            for (int q4 = 0; q4 < 4; q4++) {
                int d = d0 + q4 * 4;
                float4 kv = *(const float4*)(gk + q4 * 4);
                *(float2*)&Kd[(d + 0) * KS + 2 * c] = make_float2(kv.x, kv.x);
                *(float2*)&Kd[(d + 1) * KS + 2 * c] = make_float2(kv.y, kv.y);
                *(float2*)&Kd[(d + 2) * KS + 2 * c] = make_float2(kv.z, kv.z);
                *(float2*)&Kd[(d + 3) * KS + 2 * c] = make_float2(kv.w, kv.w);
                *(float4*)&Vs[c * VS + d] = *(const float4*)(gv + q4 * 4);
            }
        }
        __syncthreads();

        // S = Q K^T  (rows paired from Qs, cols dup'd from Kd)
        u64 accS[2][4];
#pragma unroll
        for (int rp = 0; rp < 2; rp++)
#pragma unroll
            for (int c = 0; c < 4; c++) accS[rp][c] = 0ull;
#pragma unroll 8
        for (int d = 0; d < 64; d++) {
            ulonglong2 qa  = *(const ulonglong2*)&Qs[d * QS + ty * 4];
            ulonglong2 kb0 = *(const ulonglong2*)&Kd[d * KS + tx * 8];
            ulonglong2 kb1 = *(const ulonglong2*)&Kd[d * KS + tx * 8 + 4];
            u64 bb[4] = { kb0.x, kb0.y, kb1.x, kb1.y };
#pragma unroll
            for (int c = 0; c < 4; c++) {
                ffma2(accS[0][c], qa.x, bb[c]);
                ffma2(accS[1][c], qa.y, bb[c]);
            }
        }

        float s[4][4];
#pragma unroll
        for (int rp = 0; rp < 2; rp++)
#pragma unroll
            for (int c = 0; c < 4; c++) {
                float2 v = unpk(accS[rp][c]);
                s[2 * rp][c]     = v.x * 0.125f;
                s[2 * rp + 1][c] = v.y * 0.125f;
            }
        if (j == qb) {   // causal mask on the diagonal tile
#pragma unroll
            for (int i = 0; i < 4; i++)
#pragma unroll
                for (int c = 0; c < 4; c++)
                    if (tx * 4 + c > ty * 4 + i) s[i][c] = -FLT_MAX;
        }

        __syncthreads();   // all Kd reads done before P overwrites it

        // streaming softmax (row stats replicated across the 16-lane tx group)
        float pr[4][4];
#pragma unroll
        for (int i = 0; i < 4; i++) {
            float mx = fmaxf(fmaxf(s[i][0], s[i][1]), fmaxf(s[i][2], s[i][3]));
#pragma unroll
            for (int o = 8; o >= 1; o >>= 1)
                mx = fmaxf(mx, __shfl_xor_sync(0xffffffffu, mx, o));
            float mnew  = fmaxf(mrow[i], mx);
            float alpha = __expf(mrow[i] - mnew);
            mrow[i] = mnew;
            float rs = 0.0f;
#pragma unroll
            for (int c = 0; c < 4; c++) {
                float p = __expf(s[i][c] - mnew);
                pr[i][c] = p; rs += p;
            }
#pragma unroll
            for (int o = 8; o >= 1; o >>= 1)
                rs += __shfl_xor_sync(0xffffffffu, rs, o);
            lrow[i] = lrow[i] * alpha + rs;
            u64 a2 = dup2(alpha);
            accO[i][0] = fmul2(accO[i][0], a2);
            accO[i][1] = fmul2(accO[i][1], a2);
        }

        // store P row-major, duplicated along k: Pd[r][2k]
#pragma unroll
        for (int i = 0; i < 4; i++)
#pragma unroll
            for (int c = 0; c < 4; c++)
                *(float2*)&Kd[(ty * 4 + i) * PS + (tx * 4 + c) * 2] =
                    make_float2(pr[i][c], pr[i][c]);
        __syncthreads();

        // O += P V
#pragma unroll 8
        for (int k = 0; k < 64; k++) {
            u64 pa[4];
#pragma unroll
            for (int i = 0; i < 4; i++)
                pa[i] = *(const u64*)&Kd[(ty * 4 + i) * PS + 2 * k];
            ulonglong2 vb = *(const ulonglong2*)&Vs[k * VS + tx * 4];
#pragma unroll
            for (int i = 0; i < 4; i++) {
                ffma2(accO[i][0], pa[i], vb.x);
                ffma2(accO[i][1], pa[i], vb.y);
            }
        }
        __syncthreads();   // before next tile overwrites Kd/Vs
    }

    // finalize: divide by l, write [B,T,C]
    float* ob = out + (size_t)(b * TT + qb * 64) * CDIM + h * HD;
#pragma unroll
    for (int i = 0; i < 4; i++) {
        float inv = __fdiv_rn(1.0f, lrow[i]);
        float2 o0 = unpk(accO[i][0]);
        float2 o1 = unpk(accO[i][1]);
        *(float4*)&ob[(size_t)(ty * 4 + i) * CDIM + tx * 4] =
            make_float4(o0.x * inv, o0.y * inv, o1.x * inv, o1.y * inv);
    }
}

// ---------------- launch ----------------
extern "C" void kernel_launch(void* const* d_in, const int* in_sizes, int n_in,
                              void* d_out, int out_size)
{
    const float* x       = (const float*)d_in[0];
    const float* w_attn  = (const float*)d_in[1];
    const float* b_attn  = (const float*)d_in[2];
    const float* la_attn = (const float*)d_in[3];
    const float* lb_attn = (const float*)d_in[4];
    const float* w_proj  = (const float*)d_in[5];
    const float* b_proj  = (const float*)d_in[6];
    const float* la_proj = (const float*)d_in[7];
    const float* lb_proj = (const float*)d_in[8];
    const float* ksc     = (const float*)d_in[9];
    const float* kzp     = (const float*)d_in[10];
    float* out = (float*)d_out;

    void *p_qkv, *p_attn, *p_mid, *p_mid2;
    cudaGetSymbolAddress(&p_qkv,  g_qkv);
    cudaGetSymbolAddress(&p_attn, g_attn);
    cudaGetSymbolAddress(&p_mid,  g_mid);
    cudaGetSymbolAddress(&p_mid2, g_mid2);
    float* qkv  = (float*)p_qkv;
    float* attn = (float*)p_attn;
    float* mid  = (float*)p_mid;
    float* mid2 = (float*)p_mid2;

    cudaFuncSetAttribute(attn_kernel,
                         cudaFuncAttributeMaxDynamicSharedMemorySize, ATTN_SMEM);

    // 1) LoRA mid for QKV
    lora_mid_kernel<<<MTOT / 8, 256>>>(x, la_attn, mid, CDIM);
    // 2) QKV GEMM + bias + LoRA + fake-quant on K,V columns (>= 1024)
    gemm_lora_kernel<<<dim3(N3C / 64, MTOT / 128), 256>>>(
        x, w_attn, b_attn, mid, lb_attn, qkv, N3C, CDIM, CDIM, ksc, kzp);
    // 3) causal attention
    attn_kernel<<<dim3(BB * NH, TT / 64), 256, ATTN_SMEM>>>(qkv, attn);
    // 4) LoRA mid for proj
    lora_mid_kernel<<<MTOT / 8, 256>>>(attn, la_proj, mid2, CDIM);
    // 5) output projection (no quant)
    gemm_lora_kernel<<<dim3(CDIM / 64, MTOT / 128), 256>>>(
        attn, w_proj, b_proj, mid2, lb_proj, out, CDIM, CDIM, 1 << 30, ksc, kzp);
}

// round 7
// speedup vs baseline: 3.0249x; 1.8665x over previous
#include <cuda_runtime.h>
#include <cuda_bf16.h>
#include <math.h>
#include <float.h>
#include <stdint.h>

#define BB    2
#define TT    2048
#define CDIM  1024
#define NH    16
#define HD    64
#define MTOT  (BB*TT)
#define N3C   (3*CDIM)
#define RANK  16
#define LSCALE 2.0f

typedef unsigned long long u64;

// ---------------- f32x2 helpers ----------------
__device__ __forceinline__ void ffma2(u64 &d, u64 a, u64 b) {
    asm("fma.rn.f32x2 %0, %1, %2, %0;" : "+l"(d) : "l"(a), "l"(b));
}
__device__ __forceinline__ u64 fmul2(u64 a, u64 b) {
    u64 d; asm("mul.rn.f32x2 %0, %1, %2;" : "=l"(d) : "l"(a), "l"(b)); return d;
}
__device__ __forceinline__ u64 dup2(float x) {
    u64 r; asm("mov.b64 %0, {%1, %1};" : "=l"(r) : "f"(x)); return r;
}
__device__ __forceinline__ float2 unpk(u64 v) {
    float lo, hi; asm("mov.b64 {%0, %1}, %2;" : "=f"(lo), "=f"(hi) : "l"(v));
    return make_float2(lo, hi);
}

// ---------------- portable MMA helpers (legal at compute_103) ----------------
__device__ __forceinline__ uint32_t smem_u32(const void* p) {
    uint32_t a;
    asm("{ .reg .u64 t; cvta.to.shared.u64 t, %1; cvt.u32.u64 %0, t; }" : "=r"(a) : "l"(p));
    return a;
}
__device__ __forceinline__ void cpa16(uint32_t s, const void* g) {
    asm volatile("cp.async.cg.shared.global [%0], [%1], 16;" :: "r"(s), "l"(g));
}
__device__ __forceinline__ void ldx4(uint32_t* r, uint32_t a) {
    asm volatile("ldmatrix.sync.aligned.m8n8.x4.shared.b16 {%0,%1,%2,%3}, [%4];"
        : "=r"(r[0]), "=r"(r[1]), "=r"(r[2]), "=r"(r[3]) : "r"(a));
}
__device__ __forceinline__ void mma16816(float* d, const uint32_t* a,
                                         uint32_t b0, uint32_t b1) {
    asm volatile("mma.sync.aligned.m16n8k16.row.col.f32.bf16.bf16.f32 "
        "{%0,%1,%2,%3}, {%4,%5,%6,%7}, {%8,%9}, {%0,%1,%2,%3};"
        : "+f"(d[0]), "+f"(d[1]), "+f"(d[2]), "+f"(d[3])
        : "r"(a[0]), "r"(a[1]), "r"(a[2]), "r"(a[3]), "r"(b0), "r"(b1));
}

// ---------------- scratch ----------------
__device__ float g_qkv [MTOT * N3C];
__device__ float g_attn[MTOT * CDIM];
__device__ __nv_bfloat16 g_x1[MTOT * CDIM];
__device__ __nv_bfloat16 g_x2[MTOT * CDIM];
__device__ __nv_bfloat16 g_a1[MTOT * CDIM];
__device__ __nv_bfloat16 g_a2[MTOT * CDIM];
__device__ __nv_bfloat16 g_wt1a[N3C * CDIM];
__device__ __nv_bfloat16 g_wt2a[N3C * CDIM];
__device__ __nv_bfloat16 g_wt1p[CDIM * CDIM];
__device__ __nv_bfloat16 g_wt2p[CDIM * CDIM];
__device__ float g_mid [MTOT * RANK];
__device__ float g_mid2[MTOT * RANK];

// ---------------- split x -> bf16 hi/lo ----------------
__global__ __launch_bounds__(256) void split_kernel(
    const float* __restrict__ X, __nv_bfloat16* __restrict__ X1,
    __nv_bfloat16* __restrict__ X2, int total4)
{
    int i = blockIdx.x * 256 + threadIdx.x;
    if (i >= total4) return;
    float4 v = *(const float4*)(X + (size_t)i * 4);
    float a[4] = { v.x, v.y, v.z, v.w };
#pragma unroll
    for (int j = 0; j < 4; j++) {
        __nv_bfloat16 h1 = __float2bfloat16(a[j]);
        __nv_bfloat16 h2 = __float2bfloat16(a[j] - __bfloat162float(h1));
        X1[(size_t)i * 4 + j] = h1;
        X2[(size_t)i * 4 + j] = h2;
    }
}

// ---------------- W[K][N] fp32 -> Wt[N][K] bf16 hi/lo (B^T layout for mma row.col) ----------------
__global__ __launch_bounds__(256) void wsplit_kernel(
    const float* __restrict__ W, __nv_bfloat16* __restrict__ Wt1,
    __nv_bfloat16* __restrict__ Wt2, int N, int K)
{
    __shared__ float t[32][33];
    int tx = threadIdx.x & 31, ty = threadIdx.x >> 5;
    int n0 = blockIdx.x * 32, k0 = blockIdx.y * 32;
#pragma unroll
    for (int i = 0; i < 4; i++)
        t[ty + i * 8][tx] = W[(size_t)(k0 + ty + i * 8) * N + n0 + tx];
    __syncthreads();
#pragma unroll
    for (int i = 0; i < 4; i++) {
        int n = ty + i * 8;
        float v = t[tx][n];
        __nv_bfloat16 h1 = __float2bfloat16(v);
        __nv_bfloat16 h2 = __float2bfloat16(v - __bfloat162float(h1));
        Wt1[(size_t)(n0 + n) * K + k0 + tx] = h1;
        Wt2[(size_t)(n0 + n) * K + k0 + tx] = h2;
    }
}

// ---------------- rank-16 LoRA mid, la staged in smem ----------------
__global__ __launch_bounds__(256) void lora_mid_kernel(
    const float* __restrict__ A, const float* __restrict__ la,
    float* __restrict__ out)
{
    __shared__ float las[256 * RANK];
    int tid = threadIdx.x;
    int r = tid & 15;
    int row = blockIdx.x * 16 + (tid >> 4);
    const float* arow = A + (size_t)row * CDIM;
    float acc = 0.0f;
    for (int kb = 0; kb < 4; kb++) {
        __syncthreads();
        for (int idx = tid; idx < 256 * RANK; idx += 256)
            las[idx] = la[kb * 256 * RANK + idx];
        __syncthreads();
        const float* ap = arow + kb * 256;
#pragma unroll 8
        for (int k = 0; k < 256; k += 4) {
            float4 a4 = *(const float4*)(ap + k);
            acc += a4.x * las[(k + 0) * RANK + r];
            acc += a4.y * las[(k + 1) * RANK + r];
            acc += a4.z * las[(k + 2) * RANK + r];
            acc += a4.w * las[(k + 3) * RANK + r];
        }
    }
    out[(size_t)row * RANK + r] = acc;
}

// ---------------- bf16 split GEMM on mma.sync (HMMA), fp32 accum ----------------
// C = (A1+A2)@(B1+B2)^T + bias + LSCALE*mid@lb  (A2B2 dropped, O(eps^2))
// Block 128x64, 8 warps (4x2), warp tile 32x32, BK=32, K=1024 fixed.
// smem stage: A1(10240) A2(10240) B1(5120) B2(5120) = 30720B, 2 stages = 61440B.
#define GSTG 30720
#define GEMM_SMEM (2 * GSTG)

__global__ __launch_bounds__(256) void gemm_mma_kernel(
    const __nv_bfloat16* __restrict__ A1, const __nv_bfloat16* __restrict__ A2,
    const __nv_bfloat16* __restrict__ B1, const __nv_bfloat16* __restrict__ B2,
    const float* __restrict__ bias,
    const float* __restrict__ mid, const float* __restrict__ lb,
    float* __restrict__ C, int N, int quant_start,
    const float* __restrict__ qsp, const float* __restrict__ qzp)
{
    extern __shared__ __align__(128) char sm8[];
    int tid = threadIdx.x, wid = tid >> 5, lane = tid & 31;
    int warp_m = wid & 3, warp_n = wid >> 2;
    int m0 = blockIdx.y * 128, n0 = blockIdx.x * 64;
    uint32_t sb = smem_u32(sm8);

    float acc[2][4][4];
#pragma unroll
    for (int mf = 0; mf < 2; mf++)
#pragma unroll
        for (int j = 0; j < 4; j++)
#pragma unroll
            for (int e = 0; e < 4; e++) acc[mf][j][e] = 0.0f;

    // loader: A planes: 512 chunks of 16B each (2/thread), B planes: 256 (1/thread)
    int arow0 = (tid * 2) >> 2,      acq0 = (tid * 2) & 3;        // chunk c=2*tid
    int arow1 = (tid * 2 + 1) >> 2,  acq1 = (tid * 2 + 1) & 3;
    int brow  = tid >> 2,            bcq  = tid & 3;
    const __nv_bfloat16* pA1 = A1 + (size_t)m0 * CDIM;
    const __nv_bfloat16* pA2 = A2 + (size_t)m0 * CDIM;
    const __nv_bfloat16* pB1 = B1 + (size_t)n0 * CDIM;
    const __nv_bfloat16* pB2 = B2 + (size_t)n0 * CDIM;

#define LOAD_STAGE(buf, kc) do { \
    uint32_t st_ = sb + (buf) * GSTG; \
    cpa16(st_ + arow0 * 80 + acq0 * 16,          pA1 + (size_t)arow0 * CDIM + (kc) + acq0 * 8); \
    cpa16(st_ + arow1 * 80 + acq1 * 16,          pA1 + (size_t)arow1 * CDIM + (kc) + acq1 * 8); \
    cpa16(st_ + 10240 + arow0 * 80 + acq0 * 16,  pA2 + (size_t)arow0 * CDIM + (kc) + acq0 * 8); \
    cpa16(st_ + 10240 + arow1 * 80 + acq1 * 16,  pA2 + (size_t)arow1 * CDIM + (kc) + acq1 * 8); \
    cpa16(st_ + 20480 + brow * 80 + bcq * 16,    pB1 + (size_t)brow * CDIM + (kc) + bcq * 8); \
    cpa16(st_ + 25600 + brow * 80 + bcq * 16,    pB2 + (size_t)brow * CDIM + (kc) + bcq * 8); \
    asm volatile("cp.async.commit_group;" ::: "memory"); \
} while (0)

    LOAD_STAGE(0, 0);

    for (int s = 0; s < 32; s++) {
        if (s + 1 < 32) {
            LOAD_STAGE((s + 1) & 1, (s + 1) * 32);
            asm volatile("cp.async.wait_group 1;" ::: "memory");
        } else {
            asm volatile("cp.async.wait_group 0;" ::: "memory");
        }
        __syncthreads();

        uint32_t st = sb + (s & 1) * GSTG;
        // ldmatrix base addresses
        uint32_t aoff = st + (uint32_t)(warp_m * 32 + (lane & 15)) * 80 + (uint32_t)(lane >> 4) * 16;
        uint32_t boff = st + 20480 +
            (uint32_t)(warp_n * 32 + (lane & 7) + ((lane >> 4) & 1) * 8) * 80 +
            (uint32_t)((lane >> 3) & 1) * 16;
#pragma unroll
        for (int kk = 0; kk < 2; kk++) {           // two k16 steps
            uint32_t ko = kk * 32;                  // 16 elements * 2B
            uint32_t a1f[2][4], a2f[2][4], b1f[2][4], b2f[2][4];
#pragma unroll
            for (int mf = 0; mf < 2; mf++) {
                ldx4(a1f[mf], aoff + mf * 1280 + ko);
                ldx4(a2f[mf], aoff + 10240 + mf * 1280 + ko);
            }
#pragma unroll
            for (int nf = 0; nf < 2; nf++) {
                ldx4(b1f[nf], boff + nf * 1280 + ko);
                ldx4(b2f[nf], boff + 5120 + nf * 1280 + ko);
            }
#pragma unroll
            for (int mf = 0; mf < 2; mf++)
#pragma unroll
                for (int j = 0; j < 4; j++) {
                    int nf = j >> 1, sub = (j & 1) * 2;
                    mma16816(acc[mf][j], a1f[mf], b1f[nf][sub], b1f[nf][sub + 1]);
                    mma16816(acc[mf][j], a1f[mf], b2f[nf][sub], b2f[nf][sub + 1]);
                    mma16816(acc[mf][j], a2f[mf], b1f[nf][sub], b1f[nf][sub + 1]);
                }
        }
        __syncthreads();
    }

    // ---- epilogue: bias + LoRA + optional fake-quant, direct to gmem ----
    float* sMid = (float*)sm8;            // [128][16]
    float* sLb  = (float*)(sm8 + 8192);   // [16][64]
    for (int idx = tid; idx < 128 * RANK; idx += 256) {
        int row = idx >> 4, r = idx & 15;
        sMid[idx] = mid[(size_t)(m0 + row) * RANK + r];
    }
    for (int idx = tid; idx < RANK * 64; idx += 256) {
        int r = idx >> 6, c = idx & 63;
        sLb[idx] = lb[(size_t)r * N + n0 + c];
    }
    __syncthreads();

    float qs = *qsp, qz = *qzp;
    int group = lane >> 2, tig = lane & 3;
#pragma unroll
    for (int mf = 0; mf < 2; mf++) {
#pragma unroll
        for (int half = 0; half < 2; half++) {
            int rloc = warp_m * 32 + mf * 16 + group + half * 8;
#pragma unroll
            for (int j = 0; j < 4; j++) {
                int cloc = warp_n * 32 + j * 8 + tig * 2;
                float d0 = acc[mf][j][half * 2];
                float d1 = acc[mf][j][half * 2 + 1];
                float lv0 = 0.0f, lv1 = 0.0f;
#pragma unroll
                for (int r = 0; r < RANK; r++) {
                    float mv = sMid[rloc * RANK + r];
                    lv0 += mv * sLb[r * 64 + cloc];
                    lv1 += mv * sLb[r * 64 + cloc + 1];
                }
                float v0 = d0 + bias[n0 + cloc]     + LSCALE * lv0;
                float v1 = d1 + bias[n0 + cloc + 1] + LSCALE * lv1;
                if (n0 + cloc >= quant_start) {
                    float q0 = rintf(__fdiv_rn(v0, qs) + qz);
                    q0 = fminf(fmaxf(q0, 0.0f), 255.0f);
                    v0 = (q0 - qz) * qs;
                    float q1 = rintf(__fdiv_rn(v1, qs) + qz);
                    q1 = fminf(fmaxf(q1, 0.0f), 255.0f);
                    v1 = (q1 - qz) * qs;
                }
                *(float2*)&C[(size_t)(m0 + rloc) * N + n0 + cloc] = make_float2(v0, v1);
            }
        }
    }
}

// ---------------- flash attention (f32x2, passing math) + bf16 split output ----------------
#define QS 68
#define KS 136
#define PS 132
#define VS 68
#define ATTN_SMEM ((64 * (QS + KS + VS)) * 4)

__global__ __launch_bounds__(256) void attn_kernel(
    const float* __restrict__ qkv, float* __restrict__ out,
    __nv_bfloat16* __restrict__ out1, __nv_bfloat16* __restrict__ out2)
{
    extern __shared__ __align__(16) float sm[];
    float* Qs = sm;
    float* Kd = sm + 64 * QS;
    float* Vs = Kd + 64 * KS;

    int tid = threadIdx.x;
    int tx = tid & 15, ty = tid >> 4;
    int bh = blockIdx.x;
    int b = bh >> 4, h = bh & 15;
    int qb = (int)gridDim.y - 1 - (int)blockIdx.y;

    const float* qbase = qkv + (size_t)(b * TT) * N3C + h * HD;

    {
        int r  = tid >> 2;
        int d0 = (tid & 3) * 16;
        const float* gq = qbase + (size_t)(qb * 64 + r) * N3C + d0;
#pragma unroll
        for (int c4 = 0; c4 < 4; c4++) {
            float4 v = *(const float4*)(gq + c4 * 4);
            int d = d0 + c4 * 4;
            Qs[(d + 0) * QS + r] = v.x; Qs[(d + 1) * QS + r] = v.y;
            Qs[(d + 2) * QS + r] = v.z; Qs[(d + 3) * QS + r] = v.w;
        }
    }

    u64 accO[4][2];
    float mrow[4], lrow[4];
#pragma unroll
    for (int i = 0; i < 4; i++) {
        accO[i][0] = 0ull; accO[i][1] = 0ull;
        mrow[i] = -FLT_MAX; lrow[i] = 0.0f;
    }

    for (int j = 0; j <= qb; j++) {
        {
            int c  = tid >> 2;
            int d0 = (tid & 3) * 16;
            const float* gk = qbase + CDIM     + (size_t)(j * 64 + c) * N3C + d0;
            const float* gv = qbase + 2 * CDIM + (size_t)(j * 64 + c) * N3C + d0;
#pragma unroll
            for (int q4 = 0; q4 < 4; q4++) {
                int d = d0 + q4 * 4;
                float4 kv = *(const float4*)(gk + q4 * 4);
                *(float2*)&Kd[(d + 0) * KS + 2 * c] = make_float2(kv.x, kv.x);
                *(float2*)&Kd[(d + 1) * KS + 2 * c] = make_float2(kv.y, kv.y);
                *(float2*)&Kd[(d + 2) * KS + 2 * c] = make_float2(kv.z, kv.z);
                *(float2*)&Kd[(d + 3) * KS + 2 * c] = make_float2(kv.w, kv.w);
                *(float4*)&Vs[c * VS + d] = *(const float4*)(gv + q4 * 4);
            }
        }
        __syncthreads();

        u64 accS[2][4];
#pragma unroll
        for (int rp = 0; rp < 2; rp++)
#pragma unroll
            for (int c = 0; c < 4; c++) accS[rp][c] = 0ull;
#pragma unroll 8
        for (int d = 0; d < 64; d++) {
            ulonglong2 qa  = *(const ulonglong2*)&Qs[d * QS + ty * 4];
            ulonglong2 kb0 = *(const ulonglong2*)&Kd[d * KS + tx * 8];
            ulonglong2 kb1 = *(const ulonglong2*)&Kd[d * KS + tx * 8 + 4];
            u64 bb[4] = { kb0.x, kb0.y, kb1.x, kb1.y };
#pragma unroll
            for (int c = 0; c < 4; c++) {
                ffma2(accS[0][c], qa.x, bb[c]);
                ffma2(accS[1][c], qa.y, bb[c]);
            }
        }

        float s[4][4];
#pragma unroll
        for (int rp = 0; rp < 2; rp++)
#pragma unroll
            for (int c = 0; c < 4; c++) {
                float2 v = unpk(accS[rp][c]);
                s[2 * rp][c]     = v.x * 0.125f;
                s[2 * rp + 1][c] = v.y * 0.125f;
            }
        if (j == qb) {
#pragma unroll
            for (int i = 0; i < 4; i++)
#pragma unroll
                for (int c = 0; c < 4; c++)
                    if (tx * 4 + c > ty * 4 + i) s[i][c] = -FLT_MAX;
        }

        __syncthreads();

        float pr[4][4];
#pragma unroll
        for (int i = 0; i < 4; i++) {
            float mx = fmaxf(fmaxf(s[i][0], s[i][1]), fmaxf(s[i][2], s[i][3]));
#pragma unroll
            for (int o = 8; o >= 1; o >>= 1)
                mx = fmaxf(mx, __shfl_xor_sync(0xffffffffu, mx, o));
            float mnew  = fmaxf(mrow[i], mx);
            float alpha = __expf(mrow[i] - mnew);
            mrow[i] = mnew;
            float rs = 0.0f;
#pragma unroll
            for (int c = 0; c < 4; c++) {
                float p = __expf(s[i][c] - mnew);
                pr[i][c] = p; rs += p;
            }
#pragma unroll
            for (int o = 8; o >= 1; o >>= 1)
                rs += __shfl_xor_sync(0xffffffffu, rs, o);
            lrow[i] = lrow[i] * alpha + rs;
            u64 a2 = dup2(alpha);
            accO[i][0] = fmul2(accO[i][0], a2);
            accO[i][1] = fmul2(accO[i][1], a2);
        }

#pragma unroll
        for (int i = 0; i < 4; i++)
#pragma unroll
            for (int c = 0; c < 4; c++)
                *(float2*)&Kd[(ty * 4 + i) * PS + (tx * 4 + c) * 2] =
                    make_float2(pr[i][c], pr[i][c]);
        __syncthreads();

#pragma unroll 8
        for (int k = 0; k < 64; k++) {
            u64 pa[4];
#pragma unroll
            for (int i = 0; i < 4; i++)
                pa[i] = *(const u64*)&Kd[(ty * 4 + i) * PS + 2 * k];
            ulonglong2 vb = *(const ulonglong2*)&Vs[k * VS + tx * 4];
#pragma unroll
            for (int i = 0; i < 4; i++) {
                ffma2(accO[i][0], pa[i], vb.x);
                ffma2(accO[i][1], pa[i], vb.y);
            }
        }
        __syncthreads();
    }

#pragma unroll
    for (int i = 0; i < 4; i++) {
        float inv = __fdiv_rn(1.0f, lrow[i]);
        float2 o0 = unpk(accO[i][0]);
        float2 o1 = unpk(accO[i][1]);
        float va[4] = { o0.x * inv, o0.y * inv, o1.x * inv, o1.y * inv };
        size_t base = (size_t)(b * TT + qb * 64 + ty * 4 + i) * CDIM + h * HD + tx * 4;
        *(float4*)&out[base] = make_float4(va[0], va[1], va[2], va[3]);
#pragma unroll
        for (int jj = 0; jj < 4; jj++) {
            __nv_bfloat16 h1 = __float2bfloat16(va[jj]);
            __nv_bfloat16 h2 = __float2bfloat16(va[jj] - __bfloat162float(h1));
            out1[base + jj] = h1;
            out2[base + jj] = h2;
        }
    }
}

// ---------------- launch ----------------
extern "C" void kernel_launch(void* const* d_in, const int* in_sizes, int n_in,
                              void* d_out, int out_size)
{
    const float* x       = (const float*)d_in[0];
    const float* w_attn  = (const float*)d_in[1];
    const float* b_attn  = (const float*)d_in[2];
    const float* la_attn = (const float*)d_in[3];
    const float* lb_attn = (const float*)d_in[4];
    const float* w_proj  = (const float*)d_in[5];
    const float* b_proj  = (const float*)d_in[6];
    const float* la_proj = (const float*)d_in[7];
    const float* lb_proj = (const float*)d_in[8];
    const float* ksc     = (const float*)d_in[9];
    const float* kzp     = (const float*)d_in[10];
    float* out = (float*)d_out;

    void* p;
    cudaGetSymbolAddress(&p, g_qkv);  float* qkv  = (float*)p;
    cudaGetSymbolAddress(&p, g_attn); float* attn = (float*)p;
    cudaGetSymbolAddress(&p, g_x1);   __nv_bfloat16* x1 = (__nv_bfloat16*)p;
    cudaGetSymbolAddress(&p, g_x2);   __nv_bfloat16* x2 = (__nv_bfloat16*)p;
    cudaGetSymbolAddress(&p, g_a1);   __nv_bfloat16* a1 = (__nv_bfloat16*)p;
    cudaGetSymbolAddress(&p, g_a2);   __nv_bfloat16* a2 = (__nv_bfloat16*)p;
    cudaGetSymbolAddress(&p, g_wt1a); __nv_bfloat16* wt1a = (__nv_bfloat16*)p;
    cudaGetSymbolAddress(&p, g_wt2a); __nv_bfloat16* wt2a = (__nv_bfloat16*)p;
    cudaGetSymbolAddress(&p, g_wt1p); __nv_bfloat16* wt1p = (__nv_bfloat16*)p;
    cudaGetSymbolAddress(&p, g_wt2p); __nv_bfloat16* wt2p = (__nv_bfloat16*)p;
    cudaGetSymbolAddress(&p, g_mid);  float* mid  = (float*)p;
    cudaGetSymbolAddress(&p, g_mid2); float* mid2 = (float*)p;

    cudaFuncSetAttribute(attn_kernel,
                         cudaFuncAttributeMaxDynamicSharedMemorySize, ATTN_SMEM);
    cudaFuncSetAttribute(gemm_mma_kernel,
                         cudaFuncAttributeMaxDynamicSharedMemorySize, GEMM_SMEM);

    // 8 launches/iter so ncu (-s 5 -c 1) lands on attn_kernel (launch #6)
    split_kernel<<<(MTOT * CDIM / 4 + 255) / 256, 256>>>(x, x1, x2, MTOT * CDIM / 4);
    wsplit_kernel<<<dim3(N3C / 32, CDIM / 32), 256>>>(w_attn, wt1a, wt2a, N3C, CDIM);
    wsplit_kernel<<<dim3(CDIM / 32, CDIM / 32), 256>>>(w_proj, wt1p, wt2p, CDIM, CDIM);
    lora_mid_kernel<<<MTOT / 16, 256>>>(x, la_attn, mid);
    gemm_mma_kernel<<<dim3(N3C / 64, MTOT / 128), 256, GEMM_SMEM>>>(
        x1, x2, wt1a, wt2a, b_attn, mid, lb_attn, qkv, N3C, CDIM, ksc, kzp);
    attn_kernel<<<dim3(BB * NH, TT / 64), 256, ATTN_SMEM>>>(qkv, attn, a1, a2);
    lora_mid_kernel<<<MTOT / 16, 256>>>(attn, la_proj, mid2);
    gemm_mma_kernel<<<dim3(CDIM / 64, MTOT / 128), 256, GEMM_SMEM>>>(
        a1, a2, wt1p, wt2p, b_proj, mid2, lb_proj, out, CDIM, 1 << 30, ksc, kzp);
}